// round 13
// baseline (speedup 1.0000x reference)
#include <cuda_runtime.h>
#include <cuda_bf16.h>

#define C 4096
#define MV_THREADS 256
#define KSPLIT_A 2            // matvec3 K-chunks of 2048
#define KSPLIT_OW 8           // ow K-chunks of 512
#define KW_PIN_ROWS 1536      // 1536*4096*4B = 24 MB of kw pinned (total 88 MB w/ ow)

// Scratch (allocation-free rule: __device__ globals)
__device__ float g_x3[3 * C];               // xk | xv | xr
__device__ float g_kvr_p[KSPLIT_A][3 * C];  // per-chunk partials (plain stores)
__device__ float g_rwkv[C];                 // r * wkv

// ---------------------------------------------------------------------------
// L2 evict_last load: keeps data resident in L2 across graph replays while
// evict-first (__ldcs) weight streams displace each other instead.
// ---------------------------------------------------------------------------
__device__ __forceinline__ float4 ldg_l2_keep(const float4* p, unsigned long long pol) {
    float4 v;
    asm("ld.global.nc.L2::cache_hint.v4.f32 {%0,%1,%2,%3}, [%4], %5;"
        : "=f"(v.x), "=f"(v.y), "=f"(v.z), "=f"(v.w)
        : "l"(p), "l"(pol));
    return v;
}

__device__ __forceinline__ unsigned long long l2_keep_policy() {
    unsigned long long pol;
    asm("createpolicy.fractional.L2::evict_last.b64 %0, 1.0;" : "=l"(pol));
    return pol;
}

// ---------------------------------------------------------------------------
// K1: token-shift mix + new_state copy
// ---------------------------------------------------------------------------
__global__ void mix_kernel(const float* __restrict__ x,
                           const float* __restrict__ state,
                           const float* __restrict__ tmk,
                           const float* __restrict__ tmv,
                           const float* __restrict__ tmr,
                           float* __restrict__ d_out) {
    int i = blockIdx.x * blockDim.x + threadIdx.x;
    if (i >= C) return;
    float xi = x[i];
    float si = state[i];
    g_x3[i]         = fmaf(xi - si, tmk[i], si);
    g_x3[C + i]     = fmaf(xi - si, tmv[i], si);
    g_x3[2 * C + i] = fmaf(xi - si, tmr[i], si);
    d_out[C + i] = xi;     // new_state
}

// Partial dot over CHUNK4 float4s per lane. PIN selects evict_last (L2
// resident across replays) vs evict-first streaming for the W loads.
template <int CHUNK4, bool PIN>
__device__ __forceinline__ float partial_dot(const float4* __restrict__ Wr,
                                             const float4* __restrict__ xv,
                                             int lane, unsigned long long pol) {
    float4 a0 = make_float4(0.f, 0.f, 0.f, 0.f);
    float4 a1 = make_float4(0.f, 0.f, 0.f, 0.f);
#pragma unroll
    for (int j = 0; j < CHUNK4; j += 2) {
        float4 w0 = PIN ? ldg_l2_keep(&Wr[lane + (j + 0) * 32], pol)
                        : __ldcs(&Wr[lane + (j + 0) * 32]);
        float4 w1 = PIN ? ldg_l2_keep(&Wr[lane + (j + 1) * 32], pol)
                        : __ldcs(&Wr[lane + (j + 1) * 32]);
        float4 x0 = __ldg(&xv[lane + (j + 0) * 32]);
        float4 x1 = __ldg(&xv[lane + (j + 1) * 32]);
        a0.x = fmaf(w0.x, x0.x, a0.x); a0.y = fmaf(w0.y, x0.y, a0.y);
        a0.z = fmaf(w0.z, x0.z, a0.z); a0.w = fmaf(w0.w, x0.w, a0.w);
        a1.x = fmaf(w1.x, x1.x, a1.x); a1.y = fmaf(w1.y, x1.y, a1.y);
        a1.z = fmaf(w1.z, x1.z, a1.z); a1.w = fmaf(w1.w, x1.w, a1.w);
    }
    float s = ((a0.x + a0.y) + (a0.z + a0.w))
            + ((a1.x + a1.y) + (a1.z + a1.w));
#pragma unroll
    for (int o = 16; o > 0; o >>= 1)
        s += __shfl_xor_sync(0xFFFFFFFFu, s, o);
    return s;
}

// ---------------------------------------------------------------------------
// K2: kw@xk, vw@xv, rw@xr; K split in 2 chunks of 2048.
//     grid = (512, 2, 3) = 3072 blocks. Plain store into g_kvr_p[kc].
//     kw rows [0, KW_PIN_ROWS) use evict_last -> resident across replays.
// ---------------------------------------------------------------------------
__global__ __launch_bounds__(MV_THREADS)
void matvec3_kernel(const float* __restrict__ kw,
                    const float* __restrict__ vw,
                    const float* __restrict__ rw) {
    int mat  = blockIdx.z;
    int kc   = blockIdx.y;
    const float* W = (mat == 0) ? kw : (mat == 1) ? vw : rw;

    int tid  = threadIdx.x;
    int warp = tid >> 5;
    int lane = tid & 31;
    int row  = blockIdx.x * 8 + warp;
    int col0 = kc * (C / KSPLIT_A);

    const float4* Wr = reinterpret_cast<const float4*>(W + (size_t)row * C + col0);
    const float4* xv = reinterpret_cast<const float4*>(g_x3 + mat * C + col0);

    float s;
    if (mat == 0 && row < KW_PIN_ROWS) {
        unsigned long long pol = l2_keep_policy();
        s = partial_dot<(C / KSPLIT_A) / 128, true>(Wr, xv, lane, pol);
    } else {
        s = partial_dot<(C / KSPLIT_A) / 128, false>(Wr, xv, lane, 0ull);
    }
    if (lane == 0) g_kvr_p[kc][mat * C + row] = s;
}

// ---------------------------------------------------------------------------
// K3: wkv elementwise. Sums the partials, writes new_state_a/b/p, g_rwkv,
//     zeroes out[0:C] (atomic target for K4).
// ---------------------------------------------------------------------------
__global__ void wkv_kernel(const float* __restrict__ state_a,
                           const float* __restrict__ state_b,
                           const float* __restrict__ state_p,
                           const float* __restrict__ time_first,
                           const float* __restrict__ time_decay,
                           float* __restrict__ d_out) {
    int i = blockIdx.x * blockDim.x + threadIdx.x;
    if (i >= C) return;

    float kk = 0.f, vv = 0.f, rr = 0.f;
#pragma unroll
    for (int kc = 0; kc < KSPLIT_A; kc++) {
        kk += g_kvr_p[kc][i];
        vv += g_kvr_p[kc][C + i];
        rr += g_kvr_p[kc][2 * C + i];
    }
    float aa = state_a[i];
    float bb = state_b[i];
    float pp = state_p[i];
    float tf = time_first[i];
    float td = time_decay[i];

    float r = 1.0f / (1.0f + expf(-rr));

    float ww = tf + kk;
    float p  = fmaxf(pp, ww);
    float e1 = expf(pp - p);
    float e2 = expf(ww - p);
    float a  = e1 * aa + e2 * vv;
    float b  = e1 * bb + e2;

    float ww2 = pp + td;
    float p2  = fmaxf(ww2, kk);
    float f1  = expf(ww2 - p2);
    float f2  = expf(kk - p2);

    d_out[i]         = 0.0f;               // out accumulator
    d_out[2 * C + i] = f1 * aa + f2 * vv;  // new_state_a
    d_out[3 * C + i] = f1 * bb + f2;       // new_state_b
    d_out[4 * C + i] = p2;                 // new_state_p

    g_rwkv[i] = r * (a / b);
}

// ---------------------------------------------------------------------------
// K4: out += ow @ (r*wkv); grid (512, 8) = 4096 blocks, 512-col chunks.
//     ow loaded with L2 evict_last hint -> stays resident across replays.
// ---------------------------------------------------------------------------
__global__ __launch_bounds__(MV_THREADS)
void matvec_ow_kernel(const float* __restrict__ ow,
                      float* __restrict__ out /* d_out */) {
    int tid  = threadIdx.x;
    int kc   = blockIdx.y;
    int warp = tid >> 5;
    int lane = tid & 31;
    int row  = blockIdx.x * 8 + warp;
    int col0 = kc * (C / KSPLIT_OW);

    const float4* Wr = reinterpret_cast<const float4*>(ow + (size_t)row * C + col0);
    const float4* xv = reinterpret_cast<const float4*>(g_rwkv + col0);

    unsigned long long pol = l2_keep_policy();

    float4 a0 = make_float4(0.f, 0.f, 0.f, 0.f);
    float4 a1 = make_float4(0.f, 0.f, 0.f, 0.f);
    {
        float4 w0 = ldg_l2_keep(&Wr[lane +  0], pol);
        float4 w1 = ldg_l2_keep(&Wr[lane + 32], pol);
        float4 w2 = ldg_l2_keep(&Wr[lane + 64], pol);
        float4 w3 = ldg_l2_keep(&Wr[lane + 96], pol);
        float4 x0 = __ldg(&xv[lane +  0]);
        float4 x1 = __ldg(&xv[lane + 32]);
        float4 x2 = __ldg(&xv[lane + 64]);
        float4 x3 = __ldg(&xv[lane + 96]);
        a0.x = fmaf(w0.x, x0.x, a0.x); a0.y = fmaf(w0.y, x0.y, a0.y);
        a0.z = fmaf(w0.z, x0.z, a0.z); a0.w = fmaf(w0.w, x0.w, a0.w);
        a1.x = fmaf(w1.x, x1.x, a1.x); a1.y = fmaf(w1.y, x1.y, a1.y);
        a1.z = fmaf(w1.z, x1.z, a1.z); a1.w = fmaf(w1.w, x1.w, a1.w);
        a0.x = fmaf(w2.x, x2.x, a0.x); a0.y = fmaf(w2.y, x2.y, a0.y);
        a0.z = fmaf(w2.z, x2.z, a0.z); a0.w = fmaf(w2.w, x2.w, a0.w);
        a1.x = fmaf(w3.x, x3.x, a1.x); a1.y = fmaf(w3.y, x3.y, a1.y);
        a1.z = fmaf(w3.z, x3.z, a1.z); a1.w = fmaf(w3.w, x3.w, a1.w);
    }
    float s = ((a0.x + a0.y) + (a0.z + a0.w))
            + ((a1.x + a1.y) + (a1.z + a1.w));
#pragma unroll
    for (int o = 16; o > 0; o >>= 1)
        s += __shfl_xor_sync(0xFFFFFFFFu, s, o);
    if (lane == 0) atomicAdd(&out[row], s);
}

// ---------------------------------------------------------------------------
// Launch. Input order (metadata): x, state, state_a, state_b, state_p,
// time_mix_k, time_mix_v, time_mix_r, time_first, time_decay, kw, vw, rw, ow.
// Output layout: [out | new_state | new_state_a | new_state_b | new_state_p]
// ---------------------------------------------------------------------------
extern "C" void kernel_launch(void* const* d_in, const int* in_sizes, int n_in,
                              void* d_out, int out_size) {
    const float* x   = (const float*)d_in[0];
    const float* st  = (const float*)d_in[1];
    const float* sa  = (const float*)d_in[2];
    const float* sb  = (const float*)d_in[3];
    const float* sp  = (const float*)d_in[4];
    const float* tmk = (const float*)d_in[5];
    const float* tmv = (const float*)d_in[6];
    const float* tmr = (const float*)d_in[7];
    const float* tf  = (const float*)d_in[8];
    const float* td  = (const float*)d_in[9];
    const float* kw  = (const float*)d_in[10];
    const float* vw  = (const float*)d_in[11];
    const float* rw  = (const float*)d_in[12];
    const float* ow  = (const float*)d_in[13];
    float* out = (float*)d_out;

    mix_kernel<<<C / 256, 256>>>(x, st, tmk, tmv, tmr, out);

    dim3 g2(C / 8, KSPLIT_A, 3);          // (512, 2, 3) = 3072 blocks
    matvec3_kernel<<<g2, MV_THREADS>>>(kw, vw, rw);

    wkv_kernel<<<C / 256, 256>>>(sa, sb, sp, tf, td, out);

    dim3 g4(C / 8, KSPLIT_OW);            // (512, 8) = 4096 blocks
    matvec_ow_kernel<<<g4, MV_THREADS>>>(ow, out);
}

// round 14
// speedup vs baseline: 1.0865x; 1.0865x over previous
#include <cuda_runtime.h>
#include <cuda_bf16.h>

#define C 4096
#define MV_THREADS 256
#define KSPLIT_A 2            // matvec3 K-chunks of 2048
#define KW_PIN_ROWS 1024      // 16 MB of kw pinned (total 80 MB w/ ow) — R12 knee

// Scratch (allocation-free rule: __device__ globals)
__device__ float g_x3[3 * C];               // xk | xv | xr
__device__ float g_kvr_p[KSPLIT_A][3 * C];  // per-chunk partials (plain stores)
__device__ float g_rwkv[C];                 // r * wkv

// ---------------------------------------------------------------------------
// L2 evict_last load: keeps data resident in L2 across graph replays while
// evict-first (__ldcs) weight streams displace each other instead.
// ---------------------------------------------------------------------------
__device__ __forceinline__ float4 ldg_l2_keep(const float4* p, unsigned long long pol) {
    float4 v;
    asm("ld.global.nc.L2::cache_hint.v4.f32 {%0,%1,%2,%3}, [%4], %5;"
        : "=f"(v.x), "=f"(v.y), "=f"(v.z), "=f"(v.w)
        : "l"(p), "l"(pol));
    return v;
}

__device__ __forceinline__ unsigned long long l2_keep_policy() {
    unsigned long long pol;
    asm("createpolicy.fractional.L2::evict_last.b64 %0, 1.0;" : "=l"(pol));
    return pol;
}

// ---------------------------------------------------------------------------
// K1: token-shift mix + new_state copy + zero out accumulator
// ---------------------------------------------------------------------------
__global__ void mix_kernel(const float* __restrict__ x,
                           const float* __restrict__ state,
                           const float* __restrict__ tmk,
                           const float* __restrict__ tmv,
                           const float* __restrict__ tmr,
                           float* __restrict__ d_out) {
    int i = blockIdx.x * blockDim.x + threadIdx.x;
    if (i >= C) return;
    float xi = x[i];
    float si = state[i];
    g_x3[i]         = fmaf(xi - si, tmk[i], si);
    g_x3[C + i]     = fmaf(xi - si, tmv[i], si);
    g_x3[2 * C + i] = fmaf(xi - si, tmr[i], si);
    d_out[i]     = 0.0f;   // out accumulator (ow atomics)
    d_out[C + i] = xi;     // new_state
}

// Partial dot over CHUNK4 float4s per lane. PIN selects evict_last (L2
// resident across replays) vs evict-first streaming for the W loads.
template <int CHUNK4, bool PIN>
__device__ __forceinline__ float partial_dot(const float4* __restrict__ Wr,
                                             const float4* __restrict__ xv,
                                             int lane, unsigned long long pol) {
    float4 a0 = make_float4(0.f, 0.f, 0.f, 0.f);
    float4 a1 = make_float4(0.f, 0.f, 0.f, 0.f);
#pragma unroll
    for (int j = 0; j < CHUNK4; j += 2) {
        float4 w0 = PIN ? ldg_l2_keep(&Wr[lane + (j + 0) * 32], pol)
                        : __ldcs(&Wr[lane + (j + 0) * 32]);
        float4 w1 = PIN ? ldg_l2_keep(&Wr[lane + (j + 1) * 32], pol)
                        : __ldcs(&Wr[lane + (j + 1) * 32]);
        float4 x0 = __ldg(&xv[lane + (j + 0) * 32]);
        float4 x1 = __ldg(&xv[lane + (j + 1) * 32]);
        a0.x = fmaf(w0.x, x0.x, a0.x); a0.y = fmaf(w0.y, x0.y, a0.y);
        a0.z = fmaf(w0.z, x0.z, a0.z); a0.w = fmaf(w0.w, x0.w, a0.w);
        a1.x = fmaf(w1.x, x1.x, a1.x); a1.y = fmaf(w1.y, x1.y, a1.y);
        a1.z = fmaf(w1.z, x1.z, a1.z); a1.w = fmaf(w1.w, x1.w, a1.w);
    }
    float s = ((a0.x + a0.y) + (a0.z + a0.w))
            + ((a1.x + a1.y) + (a1.z + a1.w));
#pragma unroll
    for (int o = 16; o > 0; o >>= 1)
        s += __shfl_xor_sync(0xFFFFFFFFu, s, o);
    return s;
}

// ---------------------------------------------------------------------------
// K2 (half): kw/vw/rw matvec for rows [row_base, row_base+2048).
//     grid = (256, 2, 3) = 1536 blocks per half.
// ---------------------------------------------------------------------------
__global__ __launch_bounds__(MV_THREADS)
void matvec3_half_kernel(const float* __restrict__ kw,
                         const float* __restrict__ vw,
                         const float* __restrict__ rw,
                         int row_base) {
    int mat  = blockIdx.z;
    int kc   = blockIdx.y;
    const float* W = (mat == 0) ? kw : (mat == 1) ? vw : rw;

    int tid  = threadIdx.x;
    int warp = tid >> 5;
    int lane = tid & 31;
    int row  = row_base + blockIdx.x * 8 + warp;
    int col0 = kc * (C / KSPLIT_A);

    const float4* Wr = reinterpret_cast<const float4*>(W + (size_t)row * C + col0);
    const float4* xv = reinterpret_cast<const float4*>(g_x3 + mat * C + col0);

    float s;
    if (mat == 0 && row < KW_PIN_ROWS) {
        unsigned long long pol = l2_keep_policy();
        s = partial_dot<(C / KSPLIT_A) / 128, true>(Wr, xv, lane, pol);
    } else {
        s = partial_dot<(C / KSPLIT_A) / 128, false>(Wr, xv, lane, 0ull);
    }
    if (lane == 0) g_kvr_p[kc][mat * C + row] = s;
}

// ---------------------------------------------------------------------------
// K3 (half): wkv elementwise for elems [elem_base, elem_base+2048).
//     grid = 8 blocks of 256.
// ---------------------------------------------------------------------------
__global__ void wkv_half_kernel(const float* __restrict__ state_a,
                                const float* __restrict__ state_b,
                                const float* __restrict__ state_p,
                                const float* __restrict__ time_first,
                                const float* __restrict__ time_decay,
                                float* __restrict__ d_out,
                                int elem_base) {
    int i = elem_base + blockIdx.x * blockDim.x + threadIdx.x;

    float kk = 0.f, vv = 0.f, rr = 0.f;
#pragma unroll
    for (int kc = 0; kc < KSPLIT_A; kc++) {
        kk += g_kvr_p[kc][i];
        vv += g_kvr_p[kc][C + i];
        rr += g_kvr_p[kc][2 * C + i];
    }
    float aa = state_a[i];
    float bb = state_b[i];
    float pp = state_p[i];
    float tf = time_first[i];
    float td = time_decay[i];

    float r = 1.0f / (1.0f + expf(-rr));

    float ww = tf + kk;
    float p  = fmaxf(pp, ww);
    float e1 = expf(pp - p);
    float e2 = expf(ww - p);
    float a  = e1 * aa + e2 * vv;
    float b  = e1 * bb + e2;

    float ww2 = pp + td;
    float p2  = fmaxf(ww2, kk);
    float f1  = expf(ww2 - p2);
    float f2  = expf(kk - p2);

    d_out[2 * C + i] = f1 * aa + f2 * vv;  // new_state_a
    d_out[3 * C + i] = f1 * bb + f2;       // new_state_b
    d_out[4 * C + i] = p2;                 // new_state_p

    g_rwkv[i] = r * (a / b);
}

// ---------------------------------------------------------------------------
// K4 (half): out += ow[:, cols] @ rwkv[cols] for kc in [kc_base, kc_base+4).
//     grid = (512, 4) = 2048 blocks per half; 512-col chunks.
//     ow loaded with L2 evict_last hint -> stays resident across replays.
// ---------------------------------------------------------------------------
__global__ __launch_bounds__(MV_THREADS)
void matvec_ow_half_kernel(const float* __restrict__ ow,
                           float* __restrict__ out /* d_out */,
                           int kc_base) {
    int tid  = threadIdx.x;
    int kc   = kc_base + blockIdx.y;
    int warp = tid >> 5;
    int lane = tid & 31;
    int row  = blockIdx.x * 8 + warp;
    int col0 = kc * 512;

    const float4* Wr = reinterpret_cast<const float4*>(ow + (size_t)row * C + col0);
    const float4* xv = reinterpret_cast<const float4*>(g_rwkv + col0);

    unsigned long long pol = l2_keep_policy();

    float4 a0 = make_float4(0.f, 0.f, 0.f, 0.f);
    float4 a1 = make_float4(0.f, 0.f, 0.f, 0.f);
    {
        float4 w0 = ldg_l2_keep(&Wr[lane +  0], pol);
        float4 w1 = ldg_l2_keep(&Wr[lane + 32], pol);
        float4 w2 = ldg_l2_keep(&Wr[lane + 64], pol);
        float4 w3 = ldg_l2_keep(&Wr[lane + 96], pol);
        float4 x0 = __ldg(&xv[lane +  0]);
        float4 x1 = __ldg(&xv[lane + 32]);
        float4 x2 = __ldg(&xv[lane + 64]);
        float4 x3 = __ldg(&xv[lane + 96]);
        a0.x = fmaf(w0.x, x0.x, a0.x); a0.y = fmaf(w0.y, x0.y, a0.y);
        a0.z = fmaf(w0.z, x0.z, a0.z); a0.w = fmaf(w0.w, x0.w, a0.w);
        a1.x = fmaf(w1.x, x1.x, a1.x); a1.y = fmaf(w1.y, x1.y, a1.y);
        a1.z = fmaf(w1.z, x1.z, a1.z); a1.w = fmaf(w1.w, x1.w, a1.w);
        a0.x = fmaf(w2.x, x2.x, a0.x); a0.y = fmaf(w2.y, x2.y, a0.y);
        a0.z = fmaf(w2.z, x2.z, a0.z); a0.w = fmaf(w2.w, x2.w, a0.w);
        a1.x = fmaf(w3.x, x3.x, a1.x); a1.y = fmaf(w3.y, x3.y, a1.y);
        a1.z = fmaf(w3.z, x3.z, a1.z); a1.w = fmaf(w3.w, x3.w, a1.w);
    }
    float s = ((a0.x + a0.y) + (a0.z + a0.w))
            + ((a1.x + a1.y) + (a1.z + a1.w));
#pragma unroll
    for (int o = 16; o > 0; o >>= 1)
        s += __shfl_xor_sync(0xFFFFFFFFu, s, o);
    if (lane == 0) atomicAdd(&out[row], s);
}

// ---------------------------------------------------------------------------
// Launch: fork/join two branches so branch A's ow overlaps branch B's mv3.
// Streams/events created once (host-side objects; GPU work identical per call).
// ---------------------------------------------------------------------------
static cudaStream_t s2 = nullptr;
static cudaEvent_t ev_fork = nullptr, ev_join = nullptr;

extern "C" void kernel_launch(void* const* d_in, const int* in_sizes, int n_in,
                              void* d_out, int out_size) {
    const float* x   = (const float*)d_in[0];
    const float* st  = (const float*)d_in[1];
    const float* sa  = (const float*)d_in[2];
    const float* sb  = (const float*)d_in[3];
    const float* sp  = (const float*)d_in[4];
    const float* tmk = (const float*)d_in[5];
    const float* tmv = (const float*)d_in[6];
    const float* tmr = (const float*)d_in[7];
    const float* tf  = (const float*)d_in[8];
    const float* td  = (const float*)d_in[9];
    const float* kw  = (const float*)d_in[10];
    const float* vw  = (const float*)d_in[11];
    const float* rw  = (const float*)d_in[12];
    const float* ow  = (const float*)d_in[13];
    float* out = (float*)d_out;

    if (s2 == nullptr) {
        cudaStreamCreateWithFlags(&s2, cudaStreamNonBlocking);
        cudaEventCreateWithFlags(&ev_fork, cudaEventDisableTiming);
        cudaEventCreateWithFlags(&ev_join, cudaEventDisableTiming);
    }

    // K1 on the main stream
    mix_kernel<<<C / 256, 256>>>(x, st, tmk, tmv, tmr, out);

    // fork: branch B waits on mix
    cudaEventRecord(ev_fork, 0);
    cudaStreamWaitEvent(s2, ev_fork, 0);

    dim3 gHalf(256, KSPLIT_A, 3);        // 1536 blocks per half
    dim3 gOwHalf(512, 4);                // 2048 blocks per half

    // branch A (main stream): lower rows -> lower wkv -> left ow columns
    matvec3_half_kernel<<<gHalf, MV_THREADS>>>(kw, vw, rw, 0);
    wkv_half_kernel<<<8, 256>>>(sa, sb, sp, tf, td, out, 0);
    matvec_ow_half_kernel<<<gOwHalf, MV_THREADS>>>(ow, out, 0);

    // branch B (s2): upper rows -> upper wkv -> right ow columns
    matvec3_half_kernel<<<gHalf, MV_THREADS, 0, s2>>>(kw, vw, rw, 2048);
    wkv_half_kernel<<<8, 256, 0, s2>>>(sa, sb, sp, tf, td, out, 2048);
    matvec_ow_half_kernel<<<gOwHalf, MV_THREADS, 0, s2>>>(ow, out, 4);

    // join: main stream waits on branch B
    cudaEventRecord(ev_join, s2);
    cudaStreamWaitEvent(0, ev_join, 0);
}

// round 15
// speedup vs baseline: 1.0966x; 1.0094x over previous
#include <cuda_runtime.h>
#include <cuda_bf16.h>

#define C 4096
#define MV_THREADS 256
#define KSPLIT_A 2            // matvec3 K-chunks of 2048
#define KW_PIN_ROWS 1024      // 16 MB of kw pinned (total 80 MB w/ ow) — R12 knee
#define NQ 4                  // fork/join branches (row/element quarters)

// Scratch (allocation-free rule: __device__ globals)
__device__ float g_x3[3 * C];               // xk | xv | xr
__device__ float g_kvr_p[KSPLIT_A][3 * C];  // per-chunk partials (plain stores)
__device__ float g_rwkv[C];                 // r * wkv

// ---------------------------------------------------------------------------
// L2 evict_last load: keeps data resident in L2 across graph replays while
// evict-first (__ldcs) weight streams displace each other instead.
// ---------------------------------------------------------------------------
__device__ __forceinline__ float4 ldg_l2_keep(const float4* p, unsigned long long pol) {
    float4 v;
    asm("ld.global.nc.L2::cache_hint.v4.f32 {%0,%1,%2,%3}, [%4], %5;"
        : "=f"(v.x), "=f"(v.y), "=f"(v.z), "=f"(v.w)
        : "l"(p), "l"(pol));
    return v;
}

__device__ __forceinline__ unsigned long long l2_keep_policy() {
    unsigned long long pol;
    asm("createpolicy.fractional.L2::evict_last.b64 %0, 1.0;" : "=l"(pol));
    return pol;
}

// ---------------------------------------------------------------------------
// K1: token-shift mix + new_state copy + zero out accumulator
// ---------------------------------------------------------------------------
__global__ void mix_kernel(const float* __restrict__ x,
                           const float* __restrict__ state,
                           const float* __restrict__ tmk,
                           const float* __restrict__ tmv,
                           const float* __restrict__ tmr,
                           float* __restrict__ d_out) {
    int i = blockIdx.x * blockDim.x + threadIdx.x;
    if (i >= C) return;
    float xi = x[i];
    float si = state[i];
    g_x3[i]         = fmaf(xi - si, tmk[i], si);
    g_x3[C + i]     = fmaf(xi - si, tmv[i], si);
    g_x3[2 * C + i] = fmaf(xi - si, tmr[i], si);
    d_out[i]     = 0.0f;   // out accumulator (ow atomics)
    d_out[C + i] = xi;     // new_state
}

// Partial dot over CHUNK4 float4s per lane. PIN selects evict_last (L2
// resident across replays) vs evict-first streaming for the W loads.
template <int CHUNK4, bool PIN>
__device__ __forceinline__ float partial_dot(const float4* __restrict__ Wr,
                                             const float4* __restrict__ xv,
                                             int lane, unsigned long long pol) {
    float4 a0 = make_float4(0.f, 0.f, 0.f, 0.f);
    float4 a1 = make_float4(0.f, 0.f, 0.f, 0.f);
#pragma unroll
    for (int j = 0; j < CHUNK4; j += 2) {
        float4 w0 = PIN ? ldg_l2_keep(&Wr[lane + (j + 0) * 32], pol)
                        : __ldcs(&Wr[lane + (j + 0) * 32]);
        float4 w1 = PIN ? ldg_l2_keep(&Wr[lane + (j + 1) * 32], pol)
                        : __ldcs(&Wr[lane + (j + 1) * 32]);
        float4 x0 = __ldg(&xv[lane + (j + 0) * 32]);
        float4 x1 = __ldg(&xv[lane + (j + 1) * 32]);
        a0.x = fmaf(w0.x, x0.x, a0.x); a0.y = fmaf(w0.y, x0.y, a0.y);
        a0.z = fmaf(w0.z, x0.z, a0.z); a0.w = fmaf(w0.w, x0.w, a0.w);
        a1.x = fmaf(w1.x, x1.x, a1.x); a1.y = fmaf(w1.y, x1.y, a1.y);
        a1.z = fmaf(w1.z, x1.z, a1.z); a1.w = fmaf(w1.w, x1.w, a1.w);
    }
    float s = ((a0.x + a0.y) + (a0.z + a0.w))
            + ((a1.x + a1.y) + (a1.z + a1.w));
#pragma unroll
    for (int o = 16; o > 0; o >>= 1)
        s += __shfl_xor_sync(0xFFFFFFFFu, s, o);
    return s;
}

// ---------------------------------------------------------------------------
// K2 (quarter): kw/vw/rw matvec for rows [row_base, row_base+1024).
//     grid = (128, 2, 3) = 768 blocks per quarter.
// ---------------------------------------------------------------------------
__global__ __launch_bounds__(MV_THREADS)
void matvec3_q_kernel(const float* __restrict__ kw,
                      const float* __restrict__ vw,
                      const float* __restrict__ rw,
                      int row_base) {
    int mat  = blockIdx.z;
    int kc   = blockIdx.y;
    const float* W = (mat == 0) ? kw : (mat == 1) ? vw : rw;

    int tid  = threadIdx.x;
    int warp = tid >> 5;
    int lane = tid & 31;
    int row  = row_base + blockIdx.x * 8 + warp;
    int col0 = kc * (C / KSPLIT_A);

    const float4* Wr = reinterpret_cast<const float4*>(W + (size_t)row * C + col0);
    const float4* xv = reinterpret_cast<const float4*>(g_x3 + mat * C + col0);

    float s;
    if (mat == 0 && row < KW_PIN_ROWS) {
        unsigned long long pol = l2_keep_policy();
        s = partial_dot<(C / KSPLIT_A) / 128, true>(Wr, xv, lane, pol);
    } else {
        s = partial_dot<(C / KSPLIT_A) / 128, false>(Wr, xv, lane, 0ull);
    }
    if (lane == 0) g_kvr_p[kc][mat * C + row] = s;
}

// ---------------------------------------------------------------------------
// K3 (quarter): wkv elementwise for elems [elem_base, elem_base+1024).
//     grid = 4 blocks of 256.
// ---------------------------------------------------------------------------
__global__ void wkv_q_kernel(const float* __restrict__ state_a,
                             const float* __restrict__ state_b,
                             const float* __restrict__ state_p,
                             const float* __restrict__ time_first,
                             const float* __restrict__ time_decay,
                             float* __restrict__ d_out,
                             int elem_base) {
    int i = elem_base + blockIdx.x * blockDim.x + threadIdx.x;

    float kk = 0.f, vv = 0.f, rr = 0.f;
#pragma unroll
    for (int kc = 0; kc < KSPLIT_A; kc++) {
        kk += g_kvr_p[kc][i];
        vv += g_kvr_p[kc][C + i];
        rr += g_kvr_p[kc][2 * C + i];
    }
    float aa = state_a[i];
    float bb = state_b[i];
    float pp = state_p[i];
    float tf = time_first[i];
    float td = time_decay[i];

    float r = 1.0f / (1.0f + expf(-rr));

    float ww = tf + kk;
    float p  = fmaxf(pp, ww);
    float e1 = expf(pp - p);
    float e2 = expf(ww - p);
    float a  = e1 * aa + e2 * vv;
    float b  = e1 * bb + e2;

    float ww2 = pp + td;
    float p2  = fmaxf(ww2, kk);
    float f1  = expf(ww2 - p2);
    float f2  = expf(kk - p2);

    d_out[2 * C + i] = f1 * aa + f2 * vv;  // new_state_a
    d_out[3 * C + i] = f1 * bb + f2;       // new_state_b
    d_out[4 * C + i] = p2;                 // new_state_p

    g_rwkv[i] = r * (a / b);
}

// ---------------------------------------------------------------------------
// K4 (quarter): out += ow[:, cols] @ rwkv[cols] for kc in {kc_base, kc_base+1}.
//     grid = (512, 2) = 1024 blocks per quarter; 512-col chunks.
//     ow loaded with L2 evict_last hint -> stays resident across replays.
// ---------------------------------------------------------------------------
__global__ __launch_bounds__(MV_THREADS)
void matvec_ow_q_kernel(const float* __restrict__ ow,
                        float* __restrict__ out /* d_out */,
                        int kc_base) {
    int tid  = threadIdx.x;
    int kc   = kc_base + blockIdx.y;
    int warp = tid >> 5;
    int lane = tid & 31;
    int row  = blockIdx.x * 8 + warp;
    int col0 = kc * 512;

    const float4* Wr = reinterpret_cast<const float4*>(ow + (size_t)row * C + col0);
    const float4* xv = reinterpret_cast<const float4*>(g_rwkv + col0);

    unsigned long long pol = l2_keep_policy();

    float4 a0 = make_float4(0.f, 0.f, 0.f, 0.f);
    float4 a1 = make_float4(0.f, 0.f, 0.f, 0.f);
    {
        float4 w0 = ldg_l2_keep(&Wr[lane +  0], pol);
        float4 w1 = ldg_l2_keep(&Wr[lane + 32], pol);
        float4 w2 = ldg_l2_keep(&Wr[lane + 64], pol);
        float4 w3 = ldg_l2_keep(&Wr[lane + 96], pol);
        float4 x0 = __ldg(&xv[lane +  0]);
        float4 x1 = __ldg(&xv[lane + 32]);
        float4 x2 = __ldg(&xv[lane + 64]);
        float4 x3 = __ldg(&xv[lane + 96]);
        a0.x = fmaf(w0.x, x0.x, a0.x); a0.y = fmaf(w0.y, x0.y, a0.y);
        a0.z = fmaf(w0.z, x0.z, a0.z); a0.w = fmaf(w0.w, x0.w, a0.w);
        a1.x = fmaf(w1.x, x1.x, a1.x); a1.y = fmaf(w1.y, x1.y, a1.y);
        a1.z = fmaf(w1.z, x1.z, a1.z); a1.w = fmaf(w1.w, x1.w, a1.w);
        a0.x = fmaf(w2.x, x2.x, a0.x); a0.y = fmaf(w2.y, x2.y, a0.y);
        a0.z = fmaf(w2.z, x2.z, a0.z); a0.w = fmaf(w2.w, x2.w, a0.w);
        a1.x = fmaf(w3.x, x3.x, a1.x); a1.y = fmaf(w3.y, x3.y, a1.y);
        a1.z = fmaf(w3.z, x3.z, a1.z); a1.w = fmaf(w3.w, x3.w, a1.w);
    }
    float s = ((a0.x + a0.y) + (a0.z + a0.w))
            + ((a1.x + a1.y) + (a1.z + a1.w));
#pragma unroll
    for (int o = 16; o > 0; o >>= 1)
        s += __shfl_xor_sync(0xFFFFFFFFu, s, o);
    if (lane == 0) atomicAdd(&out[row], s);
}

// ---------------------------------------------------------------------------
// Launch: 4-way fork/join. Quarter q: mv3 rows [1024q,1024q+1024) ->
// wkv elems same range -> ow kc {2q, 2q+1}. Branches fully independent
// after mix; finer granularity widens the mv3/ow overlap window.
// ---------------------------------------------------------------------------
static cudaStream_t g_s[NQ - 1] = {};
static cudaEvent_t  g_fork = nullptr;
static cudaEvent_t  g_join[NQ - 1] = {};

extern "C" void kernel_launch(void* const* d_in, const int* in_sizes, int n_in,
                              void* d_out, int out_size) {
    const float* x   = (const float*)d_in[0];
    const float* st  = (const float*)d_in[1];
    const float* sa  = (const float*)d_in[2];
    const float* sb  = (const float*)d_in[3];
    const float* sp  = (const float*)d_in[4];
    const float* tmk = (const float*)d_in[5];
    const float* tmv = (const float*)d_in[6];
    const float* tmr = (const float*)d_in[7];
    const float* tf  = (const float*)d_in[8];
    const float* td  = (const float*)d_in[9];
    const float* kw  = (const float*)d_in[10];
    const float* vw  = (const float*)d_in[11];
    const float* rw  = (const float*)d_in[12];
    const float* ow  = (const float*)d_in[13];
    float* out = (float*)d_out;

    if (g_fork == nullptr) {
        cudaEventCreateWithFlags(&g_fork, cudaEventDisableTiming);
        for (int q = 0; q < NQ - 1; q++) {
            cudaStreamCreateWithFlags(&g_s[q], cudaStreamNonBlocking);
            cudaEventCreateWithFlags(&g_join[q], cudaEventDisableTiming);
        }
    }

    // K1 on the main stream
    mix_kernel<<<C / 256, 256>>>(x, st, tmk, tmv, tmr, out);

    // fork
    cudaEventRecord(g_fork, 0);
    for (int q = 0; q < NQ - 1; q++)
        cudaStreamWaitEvent(g_s[q], g_fork, 0);

    dim3 gQ(128, KSPLIT_A, 3);           // 768 blocks per quarter
    dim3 gOwQ(512, 2);                   // 1024 blocks per quarter

    // quarter 0 on main stream; quarters 1..3 on side streams
    for (int q = 0; q < NQ; q++) {
        cudaStream_t sq = (q == 0) ? (cudaStream_t)0 : g_s[q - 1];
        matvec3_q_kernel<<<gQ, MV_THREADS, 0, sq>>>(kw, vw, rw, q * 1024);
        wkv_q_kernel<<<4, 256, 0, sq>>>(sa, sb, sp, tf, td, out, q * 1024);
        matvec_ow_q_kernel<<<gOwQ, MV_THREADS, 0, sq>>>(ow, out, q * 2);
    }

    // join: main stream waits on all side branches
    for (int q = 0; q < NQ - 1; q++) {
        cudaEventRecord(g_join[q], g_s[q]);
        cudaStreamWaitEvent(0, g_join[q], 0);
    }
}